// round 12
// baseline (speedup 1.0000x reference)
#include <cuda_runtime.h>
#include <math.h>

// Problem constants
#define NNODES 10000
#define NEDGE  160000
#define NET    170000      // edges + self loops
#define FIN    128
#define HID    512
#define NH     8
#define CHC    64
#define NCLS   10
#define NLAY   3

// ---------------- scratch (no allocation allowed) ----------------
__device__ float g_h  [NNODES * HID];
__device__ float g_o  [NNODES * HID];
__device__ float g_xl [NNODES * HID];
__device__ float g_xr [NNODES * HID];
__device__ int   g_deg [NNODES];
__device__ int   g_off [NNODES + 1];
__device__ int   g_slot[NNODES];
__device__ int   g_csrc[NET];
__device__ float g_cdist[NET];
__device__ int   g_is64;

__device__ __forceinline__ float elu_fast(float v) {
    return v > 0.f ? v : (__expf(v) - 1.f);
}

// ---------------- dtype detect + zero (fused) ----------------
__global__ void k_init(const int* ei_raw) {
    int i = blockIdx.x * blockDim.x + threadIdx.x;
    if (i < NNODES) { g_deg[i] = 0; g_slot[i] = 0; }
    if (i == 0) {
        int all_zero = 1;
        for (int j = 1; j < 64; j += 2)
            if (ei_raw[j] != 0) { all_zero = 0; break; }
        g_is64 = all_zero;
    }
}

__device__ __forceinline__ int edge_val(const void* ei, int idx) {
    if (g_is64) return (int)(((const long long*)ei)[idx]);
    return ((const int*)ei)[idx];
}

// ---------------- CSR build (edges grouped by dst) ----------------
__global__ void k_count(const void* ei) {
    int e = blockIdx.x * blockDim.x + threadIdx.x;
    if (e >= NET) return;
    int dst = (e < NEDGE) ? edge_val(ei, NEDGE + e) : (e - NEDGE);
    atomicAdd(&g_deg[dst], 1);
}

__global__ void k_scan() {
    __shared__ int part[1024];
    const int PER = (NNODES + 1023) / 1024;   // 10
    int tid = threadIdx.x;
    int base = tid * PER;
    int s = 0;
    for (int i = 0; i < PER; i++) {
        int idx = base + i;
        if (idx < NNODES) s += g_deg[idx];
    }
    part[tid] = s;
    __syncthreads();
    for (int off = 1; off < 1024; off <<= 1) {
        int v = (tid >= off) ? part[tid - off] : 0;
        __syncthreads();
        part[tid] += v;
        __syncthreads();
    }
    int run = (tid == 0) ? 0 : part[tid - 1];
    for (int i = 0; i < PER; i++) {
        int idx = base + i;
        if (idx < NNODES) { g_off[idx] = run; run += g_deg[idx]; }
    }
    if (tid == 0) g_off[NNODES] = part[1023];
}

__global__ void k_scatter(const void* ei, const float* __restrict__ dist) {
    int e = blockIdx.x * blockDim.x + threadIdx.x;
    if (e >= NET) return;
    int src, dst; float dv;
    if (e < NEDGE) {
        src = edge_val(ei, e);
        dst = edge_val(ei, NEDGE + e);
        dv  = dist[e];
    } else {
        src = dst = e - NEDGE;
        dv = 0.0f;   // FILL
    }
    int pos = g_off[dst] + atomicAdd(&g_slot[dst], 1);
    g_csrc[pos] = src;
    g_cdist[pos] = dv;
}

// ---------------- GEMM tiles: 96x64, 256 threads, 12x2 microtile ----------------
// BM=96 -> grid 105x8 = 840 tiles; at occ 2 (296 slots) waves = 840/296 = 2.84
// -> ceil 3 -> only 5.7% tail waste (vs 40% with the old 632-tile grid).
// A-fragment smem reads are 3x LDS.128 broadcast (offsets 48*ty bytes, 16B
// aligned; row stride 400 B also 16B aligned). B cols {tx, tx+32} conflict-free.
#define BM 96
#define BN 64
#define BK 16
#define AV (BM * BK / 4)   // 384 float4 per A tile

__global__ void __launch_bounds__(256, 2)
k_gemm(const float* __restrict__ A, const float* __restrict__ B,
       const float* __restrict__ bias, float* __restrict__ C,
       int M, int K, int Ncols, int act) {
    __shared__ float As[2][BK][BM + 4];
    __shared__ float Bs[2][BK][BN];
    int tid = threadIdx.x;
    int tx = tid & 31, ty = tid >> 5;
    int rowBase = blockIdx.y * BM;
    int colBase = blockIdx.x * BN;
    int a1row = tid >> 2, a1col = (tid & 3) * 4;       // idx = tid
    int a2row = (tid + 256) >> 2, a2col = ((tid + 256) & 3) * 4;
    bool hasA2 = (tid + 256) < AV;                     // tid < 128
    int brow = tid >> 4, bcol = (tid & 15) * 4;
    int gr1 = rowBase + a1row, gr2 = rowBase + a2row;

    // prologue: K-tile 0
    float4 v1 = make_float4(0.f, 0.f, 0.f, 0.f), v2 = v1;
    if (gr1 < M) v1 = *(const float4*)(A + (size_t)gr1 * K + a1col);
    if (hasA2 && gr2 < M) v2 = *(const float4*)(A + (size_t)gr2 * K + a2col);
    float4 bv = *(const float4*)(B + (size_t)brow * Ncols + colBase + bcol);
    As[0][a1col + 0][a1row] = v1.x; As[0][a1col + 1][a1row] = v1.y;
    As[0][a1col + 2][a1row] = v1.z; As[0][a1col + 3][a1row] = v1.w;
    if (hasA2) {
        As[0][a2col + 0][a2row] = v2.x; As[0][a2col + 1][a2row] = v2.y;
        As[0][a2col + 2][a2row] = v2.z; As[0][a2col + 3][a2row] = v2.w;
    }
    *(float4*)&Bs[0][brow][bcol] = bv;
    __syncthreads();

    float acc[12][2] = {};
    int buf = 0;
    for (int k0 = 0; k0 < K; k0 += BK) {
        int kn = k0 + BK;
        bool has_next = kn < K;
        float4 nv1, nv2, nbv;
        if (has_next) {
            nv1 = make_float4(0.f, 0.f, 0.f, 0.f); nv2 = nv1;
            if (gr1 < M) nv1 = *(const float4*)(A + (size_t)gr1 * K + kn + a1col);
            if (hasA2 && gr2 < M) nv2 = *(const float4*)(A + (size_t)gr2 * K + kn + a2col);
            nbv = *(const float4*)(B + (size_t)(kn + brow) * Ncols + colBase + bcol);
        }
        #pragma unroll
        for (int kk = 0; kk < BK; kk++) {
            float4 a0 = *(const float4*)&As[buf][kk][ty * 12];
            float4 a1 = *(const float4*)&As[buf][kk][ty * 12 + 4];
            float4 a2 = *(const float4*)&As[buf][kk][ty * 12 + 8];
            float a[12] = {a0.x, a0.y, a0.z, a0.w,
                           a1.x, a1.y, a1.z, a1.w,
                           a2.x, a2.y, a2.z, a2.w};
            float b0 = Bs[buf][kk][tx];
            float b1 = Bs[buf][kk][tx + 32];
            #pragma unroll
            for (int i = 0; i < 12; i++) {
                acc[i][0] += a[i] * b0;
                acc[i][1] += a[i] * b1;
            }
        }
        if (has_next) {
            int nb = buf ^ 1;
            As[nb][a1col + 0][a1row] = nv1.x; As[nb][a1col + 1][a1row] = nv1.y;
            As[nb][a1col + 2][a1row] = nv1.z; As[nb][a1col + 3][a1row] = nv1.w;
            if (hasA2) {
                As[nb][a2col + 0][a2row] = nv2.x; As[nb][a2col + 1][a2row] = nv2.y;
                As[nb][a2col + 2][a2row] = nv2.z; As[nb][a2col + 3][a2row] = nv2.w;
            }
            *(float4*)&Bs[nb][brow][bcol] = nbv;
            __syncthreads();
            buf = nb;
        }
    }
    float bb0 = bias[colBase + tx];
    float bb1 = bias[colBase + tx + 32];
    #pragma unroll
    for (int i = 0; i < 12; i++) {
        int r = rowBase + ty * 12 + i;
        if (r >= M) continue;
        float u0 = acc[i][0] + bb0;
        float u1 = acc[i][1] + bb1;
        if (act == 1) { u0 = elu_fast(u0); u1 = elu_fast(u1); }
        C[(size_t)r * Ncols + colBase + tx]      = u0;
        C[(size_t)r * Ncols + colBase + tx + 32] = u1;
    }
}

// ---------------- dual-B GEMM: Cl = A@Bl + bl, Cr = A@Br + br ----------------
__global__ void __launch_bounds__(256, 2)
k_gemm2(const float* __restrict__ A,
        const float* __restrict__ Bl, const float* __restrict__ Br,
        const float* __restrict__ bl, const float* __restrict__ br_,
        float* __restrict__ Cl, float* __restrict__ Cr, int M) {
    const int K = HID, Ncols = HID;
    __shared__ float As[2][BK][BM + 4];
    __shared__ float Bsl[2][BK][BN];
    __shared__ float Bsr[2][BK][BN];
    int tid = threadIdx.x;
    int tx = tid & 31, ty = tid >> 5;
    int rowBase = blockIdx.y * BM;
    int colBase = blockIdx.x * BN;
    int a1row = tid >> 2, a1col = (tid & 3) * 4;
    int a2row = (tid + 256) >> 2, a2col = ((tid + 256) & 3) * 4;
    bool hasA2 = (tid + 256) < AV;
    int brow = tid >> 4, bcol = (tid & 15) * 4;
    int gr1 = rowBase + a1row, gr2 = rowBase + a2row;

    float4 v1 = make_float4(0.f, 0.f, 0.f, 0.f), v2 = v1;
    if (gr1 < M) v1 = *(const float4*)(A + (size_t)gr1 * K + a1col);
    if (hasA2 && gr2 < M) v2 = *(const float4*)(A + (size_t)gr2 * K + a2col);
    float4 blv = *(const float4*)(Bl + (size_t)brow * Ncols + colBase + bcol);
    float4 brv = *(const float4*)(Br + (size_t)brow * Ncols + colBase + bcol);
    As[0][a1col + 0][a1row] = v1.x; As[0][a1col + 1][a1row] = v1.y;
    As[0][a1col + 2][a1row] = v1.z; As[0][a1col + 3][a1row] = v1.w;
    if (hasA2) {
        As[0][a2col + 0][a2row] = v2.x; As[0][a2col + 1][a2row] = v2.y;
        As[0][a2col + 2][a2row] = v2.z; As[0][a2col + 3][a2row] = v2.w;
    }
    *(float4*)&Bsl[0][brow][bcol] = blv;
    *(float4*)&Bsr[0][brow][bcol] = brv;
    __syncthreads();

    float accl[12][2] = {}, accr[12][2] = {};
    int buf = 0;
    for (int k0 = 0; k0 < K; k0 += BK) {
        int kn = k0 + BK;
        bool has_next = kn < K;
        float4 nv1, nv2, nblv, nbrv;
        if (has_next) {
            nv1 = make_float4(0.f, 0.f, 0.f, 0.f); nv2 = nv1;
            if (gr1 < M) nv1 = *(const float4*)(A + (size_t)gr1 * K + kn + a1col);
            if (hasA2 && gr2 < M) nv2 = *(const float4*)(A + (size_t)gr2 * K + kn + a2col);
            nblv = *(const float4*)(Bl + (size_t)(kn + brow) * Ncols + colBase + bcol);
            nbrv = *(const float4*)(Br + (size_t)(kn + brow) * Ncols + colBase + bcol);
        }
        #pragma unroll
        for (int kk = 0; kk < BK; kk++) {
            float4 a0 = *(const float4*)&As[buf][kk][ty * 12];
            float4 a1 = *(const float4*)&As[buf][kk][ty * 12 + 4];
            float4 a2 = *(const float4*)&As[buf][kk][ty * 12 + 8];
            float a[12] = {a0.x, a0.y, a0.z, a0.w,
                           a1.x, a1.y, a1.z, a1.w,
                           a2.x, a2.y, a2.z, a2.w};
            float l0 = Bsl[buf][kk][tx];
            float l1 = Bsl[buf][kk][tx + 32];
            float r0 = Bsr[buf][kk][tx];
            float r1 = Bsr[buf][kk][tx + 32];
            #pragma unroll
            for (int i = 0; i < 12; i++) {
                accl[i][0] += a[i] * l0;
                accl[i][1] += a[i] * l1;
                accr[i][0] += a[i] * r0;
                accr[i][1] += a[i] * r1;
            }
        }
        if (has_next) {
            int nb = buf ^ 1;
            As[nb][a1col + 0][a1row] = nv1.x; As[nb][a1col + 1][a1row] = nv1.y;
            As[nb][a1col + 2][a1row] = nv1.z; As[nb][a1col + 3][a1row] = nv1.w;
            if (hasA2) {
                As[nb][a2col + 0][a2row] = nv2.x; As[nb][a2col + 1][a2row] = nv2.y;
                As[nb][a2col + 2][a2row] = nv2.z; As[nb][a2col + 3][a2row] = nv2.w;
            }
            *(float4*)&Bsl[nb][brow][bcol] = nblv;
            *(float4*)&Bsr[nb][brow][bcol] = nbrv;
            __syncthreads();
            buf = nb;
        }
    }
    float bl0 = bl[colBase + tx],  bl1 = bl[colBase + tx + 32];
    float br0 = br_[colBase + tx], br1 = br_[colBase + tx + 32];
    #pragma unroll
    for (int i = 0; i < 12; i++) {
        int r = rowBase + ty * 12 + i;
        if (r >= M) continue;
        size_t o = (size_t)r * Ncols + colBase;
        Cl[o + tx]      = accl[i][0] + bl0;
        Cl[o + tx + 32] = accl[i][1] + bl1;
        Cr[o + tx]      = accr[i][0] + br0;
        Cr[o + tx + 32] = accr[i][1] + br1;
    }
}

// ---------------- fused GATv2 edge phase: one 128-thread block per node --------
__global__ void __launch_bounds__(128)
k_fused(const float* __restrict__ xl, const float* __restrict__ xr,
        const float* __restrict__ We, const float* __restrict__ att,
        const float* __restrict__ bias, float* __restrict__ out) {
    int node = blockIdx.x;
    int tid = threadIdx.x;
    int c = tid * 4;

    float4 xrv  = *(const float4*)(xr + (size_t)node * HID + c);
    float4 wev  = *(const float4*)(We + c);
    float4 attv = *(const float4*)(att + c);

    int s0 = g_off[node], s1 = g_off[node + 1];

    float m = -1e30f, s = 0.f;
    float4 acc = make_float4(0.f, 0.f, 0.f, 0.f);

    float dv = g_cdist[s0];
    float4 xlv = *(const float4*)(xl + (size_t)g_csrc[s0] * HID + c);

    for (int p = s0; p < s1; p++) {
        float ndv = 0.f;
        float4 nxlv = make_float4(0.f, 0.f, 0.f, 0.f);
        if (p + 1 < s1) {
            ndv = g_cdist[p + 1];
            nxlv = *(const float4*)(xl + (size_t)g_csrc[p + 1] * HID + c);
        }
        float t0 = xlv.x + xrv.x + dv * wev.x;
        float t1 = xlv.y + xrv.y + dv * wev.y;
        float t2 = xlv.z + xrv.z + dv * wev.z;
        float t3 = xlv.w + xrv.w + dv * wev.w;
        t0 = t0 > 0.f ? t0 : 0.2f * t0;
        t1 = t1 > 0.f ? t1 : 0.2f * t1;
        t2 = t2 > 0.f ? t2 : 0.2f * t2;
        t3 = t3 > 0.f ? t3 : 0.2f * t3;
        float part = t0 * attv.x + t1 * attv.y + t2 * attv.z + t3 * attv.w;
        #pragma unroll
        for (int o = 8; o; o >>= 1)
            part += __shfl_xor_sync(0xFFFFFFFFu, part, o, 16);
        float newm = fmaxf(m, part);
        float eo = __expf(m - newm);       // 0 on first edge (m = -1e30)
        float en = __expf(part - newm);
        s = s * eo + en;
        acc.x = acc.x * eo + en * xlv.x;
        acc.y = acc.y * eo + en * xlv.y;
        acc.z = acc.z * eo + en * xlv.z;
        acc.w = acc.w * eo + en * xlv.w;
        m = newm;
        dv = ndv; xlv = nxlv;
    }

    float inv = 1.0f / s;
    float4 bb = *(const float4*)(bias + c);
    float r0 = elu_fast(acc.x * inv + bb.x);
    float r1 = elu_fast(acc.y * inv + bb.y);
    float r2 = elu_fast(acc.z * inv + bb.z);
    float r3 = elu_fast(acc.w * inv + bb.w);
    *(float4*)(out + (size_t)node * HID + c) = make_float4(r0, r1, r2, r3);
}

// ---------------- classifier head + log_softmax: one warp per node ----------------
__global__ void k_final(const float* __restrict__ h, const float* __restrict__ Wa,
                        const float* __restrict__ ba, float* __restrict__ out) {
    int w = (blockIdx.x * blockDim.x + threadIdx.x) >> 5;
    int lane = threadIdx.x & 31;
    if (w >= NNODES) return;
    float acc[NCLS] = {};
    const float* hr = h + (size_t)w * HID;
    for (int c = lane; c < HID; c += 32) {
        float v = hr[c];
        const float* wr = Wa + c * NCLS;
        #pragma unroll
        for (int k = 0; k < NCLS; k++) acc[k] += v * wr[k];
    }
    #pragma unroll
    for (int k = 0; k < NCLS; k++)
        #pragma unroll
        for (int o = 16; o; o >>= 1) acc[k] += __shfl_xor_sync(0xFFFFFFFFu, acc[k], o);
    if (lane == 0) {
        float m = -1e30f;
        #pragma unroll
        for (int k = 0; k < NCLS; k++) { acc[k] += ba[k]; m = fmaxf(m, acc[k]); }
        float s = 0.f;
        #pragma unroll
        for (int k = 0; k < NCLS; k++) s += expf(acc[k] - m);
        float ls = logf(s);
        #pragma unroll
        for (int k = 0; k < NCLS; k++) out[(size_t)w * NCLS + k] = acc[k] - m - ls;
    }
}

// ---------------- driver ----------------
// Launch order puts the first k_gemm2 at global launch index 5 (harness issues
// 2 launches first), so the ncu -s 5 -c 1 capture profiles the dominant kernel.
// CSR scan/scatter are deferred until after it (only k_fused needs them).
extern "C" void kernel_launch(void* const* d_in, const int* in_sizes, int n_in,
                              void* d_out, int out_size) {
    const float* x    = (const float*)d_in[0];
    const void*  ei   = d_in[1];                 // int32 or int64, detected on device
    const float* dist = (const float*)d_in[2];
    const float* Wb   = (const float*)d_in[3];
    const float* bb   = (const float*)d_in[4];
    const float* Wl   = (const float*)d_in[5];
    const float* bl   = (const float*)d_in[6];
    const float* Wr   = (const float*)d_in[7];
    const float* br   = (const float*)d_in[8];
    const float* We   = (const float*)d_in[9];
    const float* att  = (const float*)d_in[10];
    const float* bc   = (const float*)d_in[11];
    const float* Wa   = (const float*)d_in[12];
    const float* ba   = (const float*)d_in[13];
    float* out = (float*)d_out;

    float *ph, *po, *pxl, *pxr;
    cudaGetSymbolAddress((void**)&ph,  g_h);
    cudaGetSymbolAddress((void**)&po,  g_o);
    cudaGetSymbolAddress((void**)&pxl, g_xl);
    cudaGetSymbolAddress((void**)&pxr, g_xr);

    dim3 gB(HID / BN, (NNODES + BM - 1) / BM);

    k_init<<<(NNODES + 255) / 256, 256>>>((const int*)ei);          // idx 2
    k_count<<<(NET + 255) / 256, 256>>>(ei);                         // idx 3
    k_gemm<<<gB, 256>>>(x, Wb, bb, ph, NNODES, FIN, HID, 1);         // idx 4
    k_gemm2<<<gB, 256>>>(ph, Wl, Wr, bl, br, pxl, pxr, NNODES);      // idx 5 (profiled)
    k_scan<<<1, 1024>>>();                                           // idx 6
    k_scatter<<<(NET + 255) / 256, 256>>>(ei, dist);                 // idx 7
    k_fused<<<NNODES, 128>>>(pxl, pxr, We, att, bc, po);             // layer 0 out -> g_o

    float* cur = po;
    float* nxt = ph;
    for (int l = 1; l < NLAY; l++) {
        k_gemm2<<<gB, 256>>>(cur,
                             Wl + (size_t)l * HID * HID, Wr + (size_t)l * HID * HID,
                             bl + l * HID, br + l * HID,
                             pxl, pxr, NNODES);
        k_fused<<<NNODES, 128>>>(pxl, pxr, We + l * HID, att + l * HID,
                                 bc + l * HID, nxt);
        float* t = cur; cur = nxt; nxt = t;
    }

    // classifier + log_softmax
    k_final<<<(NNODES * 32 + 255) / 256, 256>>>(cur, Wa, ba, out);
}